// round 6
// baseline (speedup 1.0000x reference)
#include <cuda_runtime.h>
#include <cuda_fp16.h>
#include <stdint.h>

typedef __half f16;

#define BATCH 4
#define SEQ   2048
#define DMOD  1024

// ----------------------------------------------------------------------------
// Scratch (device globals; allocation is forbidden)
// ----------------------------------------------------------------------------
#define NQ ((long)BATCH*SEQ*DMOD)   // 8,388,608
#define NW ((long)DMOD*DMOD)        // 1,048,576
#define NS ((long)BATCH*SEQ*SEQ)    // 16,777,216

__device__ __align__(256) f16 g_xq_hi[NQ], g_xq_lo[NQ];
__device__ __align__(256) f16 g_xk_hi[NQ], g_xk_lo[NQ];
__device__ __align__(256) f16 g_xv_hi[NQ], g_xv_lo[NQ];
__device__ __align__(256) f16 g_wq_hi[NW], g_wq_lo[NW];
__device__ __align__(256) f16 g_wk_hi[NW], g_wk_lo[NW];
__device__ __align__(256) f16 g_wv_hi[NW], g_wv_lo[NW];
__device__ __align__(256) f16 g_wo_hi[NW], g_wo_lo[NW];
__device__ __align__(256) f16 g_qp_hi[NQ], g_qp_lo[NQ];
__device__ __align__(256) f16 g_kp_hi[NQ], g_kp_lo[NQ];
__device__ __align__(256) f16 g_vT_hi[NQ], g_vT_lo[NQ];   // [B][D][S]
__device__ __align__(256) float g_sc[NS];                 // scores fp32
__device__ __align__(256) f16 g_at[NS];                   // probs single
__device__ __align__(256) f16 g_av_hi[NQ], g_av_lo[NQ];   // attn@V pair

// ----------------------------------------------------------------------------
// helpers
// ----------------------------------------------------------------------------
__device__ __forceinline__ uint32_t smem_u32(const void* p) {
    uint32_t a;
    asm("{ .reg .u64 t; cvta.to.shared.u64 t, %1; cvt.u32.u64 %0, t; }" : "=r"(a) : "l"(p));
    return a;
}
__device__ __forceinline__ void cp16(uint32_t s, const void* g) {
    asm volatile("cp.async.cg.shared.global [%0], [%1], 16;" :: "r"(s), "l"(g));
}
#define CP_COMMIT() asm volatile("cp.async.commit_group;" ::: "memory")
#define CP_WAIT(n)  asm volatile("cp.async.wait_group %0;" :: "n"(n) : "memory")

__device__ __forceinline__ void ldsm4(uint32_t& r0, uint32_t& r1, uint32_t& r2,
                                      uint32_t& r3, uint32_t addr) {
    asm volatile("ldmatrix.sync.aligned.m8n8.x4.shared.b16 {%0,%1,%2,%3}, [%4];"
                 : "=r"(r0), "=r"(r1), "=r"(r2), "=r"(r3) : "r"(addr));
}
__device__ __forceinline__ void mma16816(float* d, const uint32_t* a, const uint32_t* b) {
    asm volatile(
        "mma.sync.aligned.m16n8k16.row.col.f32.f16.f16.f32 "
        "{%0,%1,%2,%3}, {%4,%5,%6,%7}, {%8,%9}, {%0,%1,%2,%3};"
        : "+f"(d[0]), "+f"(d[1]), "+f"(d[2]), "+f"(d[3])
        : "r"(a[0]), "r"(a[1]), "r"(a[2]), "r"(a[3]), "r"(b[0]), "r"(b[1]));
}

// ----------------------------------------------------------------------------
// conversions
// ----------------------------------------------------------------------------
__global__ void split_f16(const float* __restrict__ x, f16* __restrict__ hi,
                          f16* __restrict__ lo, long n) {
    long i = (long)blockIdx.x * blockDim.x + threadIdx.x;
    if (i < n) {
        float v = x[i];
        f16 h = __float2half_rn(v);
        hi[i] = h;
        lo[i] = __float2half_rn(v - __half2float(h));
    }
}

// split Wq, Wk, Wv in one launch
__global__ void split_w3(const float* __restrict__ wq, const float* __restrict__ wk,
                         const float* __restrict__ wv) {
    long i = (long)blockIdx.x * blockDim.x + threadIdx.x;
    if (i >= 3 * NW) return;
    const float* src; f16 *hi, *lo; long j;
    if (i < NW)           { src = wq; hi = g_wq_hi; lo = g_wq_lo; j = i; }
    else if (i < 2 * NW)  { src = wk; hi = g_wk_hi; lo = g_wk_lo; j = i - NW; }
    else                  { src = wv; hi = g_wv_hi; lo = g_wv_lo; j = i - 2 * NW; }
    float v = src[j];
    f16 h = __float2half_rn(v);
    hi[j] = h;
    lo[j] = __float2half_rn(v - __half2float(h));
}

// ----------------------------------------------------------------------------
// Row softmax fp32 -> fp16 single  (n == 2048, 256 threads)
// ----------------------------------------------------------------------------
__global__ void softmax_f16(const float* __restrict__ S, f16* __restrict__ P, int n) {
    const float* row = S + (long)blockIdx.x * n;
    __shared__ float red[256];
    const int t = threadIdx.x;
    float e[8];
    float m = -1e30f;
#pragma unroll
    for (int i = 0; i < 8; i++) { e[i] = row[t + i * 256]; m = fmaxf(m, e[i]); }
    red[t] = m; __syncthreads();
    for (int s = 128; s > 0; s >>= 1) {
        if (t < s) red[t] = fmaxf(red[t], red[t + s]);
        __syncthreads();
    }
    m = red[0]; __syncthreads();
    float sum = 0.f;
#pragma unroll
    for (int i = 0; i < 8; i++) { e[i] = __expf(e[i] - m); sum += e[i]; }
    red[t] = sum; __syncthreads();
    for (int s = 128; s > 0; s >>= 1) {
        if (t < s) red[t] += red[t + s];
        __syncthreads();
    }
    float inv = 1.0f / red[0];
#pragma unroll
    for (int i = 0; i < 8; i++)
        P[(long)blockIdx.x * n + t + i * 256] = __float2half_rn(e[i] * inv);
}

// ----------------------------------------------------------------------------
// GEMM body (NT): acc[m,n] += sum_k A[m,k]*B[n,k]
//   PROD==3: (Ah+Al)x(Bh+Bl) 3-product.  PROD==2: Ah x (Bh+Bl).
//   CTA 128x128, BK=64, 2-stage cp.async, 8 warps (64x32 each).
// ----------------------------------------------------------------------------
#define ROWB 144               // 128B data + 16B pad
#define TILEB (128 * ROWB)     // 18432

template <int PROD>
__device__ __forceinline__ void gemm_body(
    const f16* __restrict__ pAh, const f16* __restrict__ pAl,
    const f16* __restrict__ pBh, const f16* __restrict__ pBl,
    int K, int m0, int n0, char* smem, float (&acc)[4][4][4])
{
    constexpr int NTILE  = PROD + 1;
    constexpr int OFF_AH = 0;
    constexpr int OFF_AL = TILEB;                        // only used when PROD==3
    constexpr int OFF_BH = (PROD == 3) ? 2 * TILEB : TILEB;
    constexpr int OFF_BL = OFF_BH + TILEB;
    constexpr int STAGE  = NTILE * TILEB;

    const uint32_t sb = smem_u32(smem);
    const int tid = threadIdx.x;
    const int wid = tid >> 5;
    const int lid = tid & 31;
    const int wm = (wid & 1) * 64;
    const int wn = (wid >> 1) * 32;

    const int lrow  = tid >> 1;          // 0..127
    const int lhalf = (tid & 1) * 4;     // 16B-chunk base 0 or 4

#pragma unroll
    for (int i = 0; i < 4; ++i)
#pragma unroll
        for (int j = 0; j < 4; ++j)
#pragma unroll
            for (int c = 0; c < 4; ++c) acc[i][j][c] = 0.f;

    const int nch = K / 64;

    auto issue = [&](int ch, int buf) {
        const int k0 = ch * 64;
        const uint32_t s0 = sb + buf * STAGE;
        const uint32_t so = (uint32_t)(lrow * ROWB + lhalf * 16);
        const long gA = (long)(m0 + lrow) * K + k0 + lhalf * 8;
        const long gB = (long)(n0 + lrow) * K + k0 + lhalf * 8;
#pragma unroll
        for (int j = 0; j < 4; ++j) {
            cp16(s0 + OFF_AH + so + j * 16, pAh + gA + j * 8);
            if (PROD == 3) cp16(s0 + OFF_AL + so + j * 16, pAl + gA + j * 8);
            cp16(s0 + OFF_BH + so + j * 16, pBh + gB + j * 8);
            cp16(s0 + OFF_BL + so + j * 16, pBl + gB + j * 8);
        }
    };

    issue(0, 0);
    CP_COMMIT();

    const int a_row = lid & 15;
    const int a_col = (lid >> 4) * 16;
    const int b_nin = ((lid >> 4) & 1) * 8 + (lid & 7);
    const int b_col = ((lid >> 3) & 1) * 16;

    for (int ch = 0; ch < nch; ++ch) {
        if (ch + 1 < nch) { issue(ch + 1, (ch + 1) & 1); CP_COMMIT(); CP_WAIT(1); }
        else              { CP_WAIT(0); }
        __syncthreads();

        const uint32_t s0 = sb + (ch & 1) * STAGE;

#pragma unroll
        for (int ks = 0; ks < 4; ++ks) {
            const int kb = ks * 32 + a_col;
            uint32_t ah[4][4], al[4][4];
#pragma unroll
            for (int mt = 0; mt < 4; ++mt) {
                const uint32_t ro = (uint32_t)((wm + mt * 16 + a_row) * ROWB);
                ldsm4(ah[mt][0], ah[mt][1], ah[mt][2], ah[mt][3], s0 + OFF_AH + ro + kb);
                if (PROD == 3)
                    ldsm4(al[mt][0], al[mt][1], al[mt][2], al[mt][3], s0 + OFF_AL + ro + kb);
            }
            uint32_t bh[2][4], bl[2][4];
#pragma unroll
            for (int np = 0; np < 2; ++np) {
                const uint32_t ro = (uint32_t)((wn + np * 16 + b_nin) * ROWB + ks * 32 + b_col);
                ldsm4(bh[np][0], bh[np][1], bh[np][2], bh[np][3], s0 + OFF_BH + ro);
                ldsm4(bl[np][0], bl[np][1], bl[np][2], bl[np][3], s0 + OFF_BL + ro);
            }
#pragma unroll
            for (int mt = 0; mt < 4; ++mt) {
#pragma unroll
                for (int nt = 0; nt < 4; ++nt) {
                    const int np = nt >> 1, sel = (nt & 1) * 2;
                    mma16816(acc[mt][nt], ah[mt], &bh[np][sel]);
                    mma16816(acc[mt][nt], ah[mt], &bl[np][sel]);
                    if (PROD == 3)
                        mma16816(acc[mt][nt], al[mt], &bh[np][sel]);
                }
            }
        }
        __syncthreads();
    }
}

#define SMEM3 (2 * 4 * TILEB)   // 147456
#define SMEM2 (2 * 3 * TILEB)   // 110592

// epilogue index helpers (per acc element)
#define EPI_LOOP(body)                                                        \
    const int gr = lid >> 2, tg = lid & 3;                                    \
    _Pragma("unroll")                                                         \
    for (int mt = 0; mt < 4; ++mt)                                            \
    _Pragma("unroll")                                                         \
    for (int nt = 0; nt < 4; ++nt)                                            \
    _Pragma("unroll")                                                         \
    for (int h = 0; h < 2; ++h)                                               \
    _Pragma("unroll")                                                         \
    for (int c = 0; c < 2; ++c) {                                             \
        const int mloc = wm + mt * 16 + gr + h * 8;                           \
        const int nloc = wn + nt * 8 + tg * 2 + c;                            \
        float v = acc[mt][nt][h * 2 + c];                                     \
        body                                                                  \
    }

// ---- fused QKV projection: 3P, region-dispatched ----
__global__ void __launch_bounds__(256) qkv3(
    const float* __restrict__ bq, const float* __restrict__ bk,
    const float* __restrict__ bv)
{
    extern __shared__ char smem[];
    const int region = blockIdx.x >> 3;          // 0=q 1=k 2=v
    const int n0 = (blockIdx.x & 7) * 128;       // within weight
    const int m0 = blockIdx.y * 128;
    const int tid = threadIdx.x, wid = tid >> 5, lid = tid & 31;
    const int wm = (wid & 1) * 64, wn = (wid >> 1) * 32;

    const f16 *Ah, *Al, *Bh, *Bl;
    const float* bias;
    if (region == 0)      { Ah = g_xq_hi; Al = g_xq_lo; Bh = g_wq_hi; Bl = g_wq_lo; bias = bq; }
    else if (region == 1) { Ah = g_xk_hi; Al = g_xk_lo; Bh = g_wk_hi; Bl = g_wk_lo; bias = bk; }
    else                  { Ah = g_xv_hi; Al = g_xv_lo; Bh = g_wv_hi; Bl = g_wv_lo; bias = bv; }

    float acc[4][4][4];
    gemm_body<3>(Ah, Al, Bh, Bl, DMOD, m0, n0, smem, acc);

    EPI_LOOP({
        const int m = m0 + mloc;
        const int n = n0 + nloc;
        v += __ldg(bias + n);
        f16 hh = __float2half_rn(v);
        f16 ll = __float2half_rn(v - __half2float(hh));
        if (region == 0) {
            long o = (long)m * DMOD + n;
            g_qp_hi[o] = hh; g_qp_lo[o] = ll;
        } else if (region == 1) {
            long o = (long)m * DMOD + n;
            g_kp_hi[o] = hh; g_kp_lo[o] = ll;
        } else {
            long o = (long)(m >> 11) * DMOD * SEQ + (long)n * SEQ + (m & 2047);
            g_vT_hi[o] = hh; g_vT_lo[o] = ll;
        }
    })
}

// ---- scores = qp @ kp^T * 0.125 : 3P -> fp32 ----
__global__ void __launch_bounds__(256) scores3() {
    extern __shared__ char smem[];
    const long bz = blockIdx.z;
    const int m0 = blockIdx.y * 128, n0 = blockIdx.x * 128;
    const int tid = threadIdx.x, wid = tid >> 5, lid = tid & 31;
    const int wm = (wid & 1) * 64, wn = (wid >> 1) * 32;
    const long ob = bz * (long)SEQ * DMOD;

    float acc[4][4][4];
    gemm_body<3>(g_qp_hi + ob, g_qp_lo + ob, g_kp_hi + ob, g_kp_lo + ob,
                 DMOD, m0, n0, smem, acc);

    float* C = g_sc + bz * (long)SEQ * SEQ;
    EPI_LOOP({
        C[(long)(m0 + mloc) * SEQ + n0 + nloc] = v * 0.125f;
    })
}

// ---- att = probs @ vT^T : 2P -> fp16 pair ----
__global__ void __launch_bounds__(256) av2() {
    extern __shared__ char smem[];
    const long bz = blockIdx.z;
    const int m0 = blockIdx.y * 128, n0 = blockIdx.x * 128;
    const int tid = threadIdx.x, wid = tid >> 5, lid = tid & 31;
    const int wm = (wid & 1) * 64, wn = (wid >> 1) * 32;

    float acc[4][4][4];
    gemm_body<2>(g_at + bz * (long)SEQ * SEQ, nullptr,
                 g_vT_hi + bz * (long)DMOD * SEQ, g_vT_lo + bz * (long)DMOD * SEQ,
                 SEQ, m0, n0, smem, acc);

    const long cb = bz * (long)SEQ * DMOD;
    EPI_LOOP({
        long o = cb + (long)(m0 + mloc) * DMOD + n0 + nloc;
        f16 hh = __float2half_rn(v);
        g_av_hi[o] = hh;
        g_av_lo[o] = __float2half_rn(v - __half2float(hh));
    })
}

// ---- out = av @ Wo^T + bo : 3P -> fp32 ----
__global__ void __launch_bounds__(256) out3(const float* __restrict__ bo,
                                            float* __restrict__ out) {
    extern __shared__ char smem[];
    const int m0 = blockIdx.y * 128, n0 = blockIdx.x * 128;
    const int tid = threadIdx.x, wid = tid >> 5, lid = tid & 31;
    const int wm = (wid & 1) * 64, wn = (wid >> 1) * 32;

    float acc[4][4][4];
    gemm_body<3>(g_av_hi, g_av_lo, g_wo_hi, g_wo_lo, DMOD, m0, n0, smem, acc);

    EPI_LOOP({
        const int n = n0 + nloc;
        out[(long)(m0 + mloc) * DMOD + n] = v + __ldg(bo + n);
    })
}

// ----------------------------------------------------------------------------
// launch
// ----------------------------------------------------------------------------
extern "C" void kernel_launch(void* const* d_in, const int* in_sizes, int n_in,
                              void* d_out, int out_size) {
    const float* q  = (const float*)d_in[0];
    const float* k  = (const float*)d_in[1];
    const float* v  = (const float*)d_in[2];
    const float* Wq = (const float*)d_in[3];
    const float* bq = (const float*)d_in[4];
    const float* Wk = (const float*)d_in[5];
    const float* bk = (const float*)d_in[6];
    const float* Wv = (const float*)d_in[7];
    const float* bv = (const float*)d_in[8];
    const float* Wo = (const float*)d_in[9];
    const float* bo = (const float*)d_in[10];
    float* out = (float*)d_out;

    f16 *xqh, *xql, *xkh, *xkl, *xvh, *xvl, *woh, *wol;
    float* sc; f16* at;
    cudaGetSymbolAddress((void**)&xqh, g_xq_hi); cudaGetSymbolAddress((void**)&xql, g_xq_lo);
    cudaGetSymbolAddress((void**)&xkh, g_xk_hi); cudaGetSymbolAddress((void**)&xkl, g_xk_lo);
    cudaGetSymbolAddress((void**)&xvh, g_xv_hi); cudaGetSymbolAddress((void**)&xvl, g_xv_lo);
    cudaGetSymbolAddress((void**)&woh, g_wo_hi); cudaGetSymbolAddress((void**)&wol, g_wo_lo);
    cudaGetSymbolAddress((void**)&sc,  g_sc);
    cudaGetSymbolAddress((void**)&at,  g_at);

    cudaFuncSetAttribute(qkv3,    cudaFuncAttributeMaxDynamicSharedMemorySize, SMEM3);
    cudaFuncSetAttribute(scores3, cudaFuncAttributeMaxDynamicSharedMemorySize, SMEM3);
    cudaFuncSetAttribute(av2,     cudaFuncAttributeMaxDynamicSharedMemorySize, SMEM2);
    cudaFuncSetAttribute(out3,    cudaFuncAttributeMaxDynamicSharedMemorySize, SMEM3);

    const int S = SEQ, B = BATCH;
    dim3 blk(256);

    // launches 1-5 (so ncu -s 5 -c 1 captures qkv3)
    split_f16<<<(unsigned)((NQ + 511) / 512), 512>>>(q, xqh, xql, NQ);       // 1
    split_f16<<<(unsigned)((NQ + 511) / 512), 512>>>(k, xkh, xkl, NQ);       // 2
    split_f16<<<(unsigned)((NQ + 511) / 512), 512>>>(v, xvh, xvl, NQ);       // 3
    split_w3 <<<(unsigned)((3 * NW + 511) / 512), 512>>>(Wq, Wk, Wv);        // 4
    split_f16<<<(unsigned)((NW + 511) / 512), 512>>>(Wo, woh, wol, NW);      // 5

    // 6: fused QKV projections (3P)
    qkv3<<<dim3(24, 64), blk, SMEM3>>>(bq, bk, bv);
    // 7: scores (3P)
    scores3<<<dim3(16, 16, B), blk, SMEM3>>>();
    // 8: softmax
    softmax_f16<<<(unsigned)(B * S), 256>>>(sc, at, S);
    // 9: attn @ V (2P)
    av2<<<dim3(8, 16, B), blk, SMEM2>>>();
    // 10: output projection (3P)
    out3<<<dim3(8, 64), blk, SMEM3>>>(bo, out);
}

// round 7
// speedup vs baseline: 1.4927x; 1.4927x over previous
#include <cuda_runtime.h>
#include <cuda_fp16.h>
#include <stdint.h>

typedef __half f16;

#define BATCH 4
#define SEQ   2048
#define DMOD  1024

// ----------------------------------------------------------------------------
// Scratch (device globals; allocation is forbidden)
// ----------------------------------------------------------------------------
#define NQ ((long)BATCH*SEQ*DMOD)   // 8,388,608
#define NW ((long)DMOD*DMOD)        // 1,048,576
#define NS ((long)BATCH*SEQ*SEQ)    // 16,777,216

__device__ __align__(256) f16 g_xq[NQ], g_xk[NQ], g_xv[NQ];        // inputs, single fp16
__device__ __align__(256) f16 g_wq_hi[NW], g_wq_lo[NW];
__device__ __align__(256) f16 g_wk_hi[NW], g_wk_lo[NW];
__device__ __align__(256) f16 g_wv_hi[NW], g_wv_lo[NW];
__device__ __align__(256) f16 g_wo_hi[NW], g_wo_lo[NW];
__device__ __align__(256) f16 g_qp[NQ];                            // q-proj, single
__device__ __align__(256) f16 g_kp_hi[NQ], g_kp_lo[NQ];            // k-proj, pair
__device__ __align__(256) f16 g_vT_hi[NQ], g_vT_lo[NQ];            // v-proj transposed [B][D][S], pair
__device__ __align__(256) float g_sc[NS];                          // scores fp32
__device__ __align__(256) f16 g_at[NS];                            // probs, single
__device__ __align__(256) f16 g_av[NQ];                            // attn@V, single

// ----------------------------------------------------------------------------
// helpers
// ----------------------------------------------------------------------------
__device__ __forceinline__ uint32_t smem_u32(const void* p) {
    uint32_t a;
    asm("{ .reg .u64 t; cvta.to.shared.u64 t, %1; cvt.u32.u64 %0, t; }" : "=r"(a) : "l"(p));
    return a;
}
__device__ __forceinline__ void cp16(uint32_t s, const void* g) {
    asm volatile("cp.async.cg.shared.global [%0], [%1], 16;" :: "r"(s), "l"(g));
}
#define CP_COMMIT() asm volatile("cp.async.commit_group;" ::: "memory")
#define CP_WAIT(n)  asm volatile("cp.async.wait_group %0;" :: "n"(n) : "memory")

__device__ __forceinline__ void ldsm4(uint32_t& r0, uint32_t& r1, uint32_t& r2,
                                      uint32_t& r3, uint32_t addr) {
    asm volatile("ldmatrix.sync.aligned.m8n8.x4.shared.b16 {%0,%1,%2,%3}, [%4];"
                 : "=r"(r0), "=r"(r1), "=r"(r2), "=r"(r3) : "r"(addr));
}
__device__ __forceinline__ void mma16816(float* d, const uint32_t* a, const uint32_t* b) {
    asm volatile(
        "mma.sync.aligned.m16n8k16.row.col.f32.f16.f16.f32 "
        "{%0,%1,%2,%3}, {%4,%5,%6,%7}, {%8,%9}, {%0,%1,%2,%3};"
        : "+f"(d[0]), "+f"(d[1]), "+f"(d[2]), "+f"(d[3])
        : "r"(a[0]), "r"(a[1]), "r"(a[2]), "r"(a[3]), "r"(b[0]), "r"(b[1]));
}

// ----------------------------------------------------------------------------
// fused conversions
// ----------------------------------------------------------------------------
// q,k,v -> single fp16 in one launch
__global__ void conv_x3(const float* __restrict__ q, const float* __restrict__ k,
                        const float* __restrict__ v) {
    long i = (long)blockIdx.x * blockDim.x + threadIdx.x;
    if (i >= 3 * NQ) return;
    const float* src; f16* dst; long j;
    if (i < NQ)          { src = q; dst = g_xq; j = i; }
    else if (i < 2 * NQ) { src = k; dst = g_xk; j = i - NQ; }
    else                 { src = v; dst = g_xv; j = i - 2 * NQ; }
    dst[j] = __float2half_rn(src[j]);
}

// Wq,Wk,Wv,Wo -> fp16 hi/lo pairs in one launch
__global__ void split_w4(const float* __restrict__ wq, const float* __restrict__ wk,
                         const float* __restrict__ wv, const float* __restrict__ wo) {
    long i = (long)blockIdx.x * blockDim.x + threadIdx.x;
    if (i >= 4 * NW) return;
    const float* src; f16 *hi, *lo; long j;
    if (i < NW)          { src = wq; hi = g_wq_hi; lo = g_wq_lo; j = i; }
    else if (i < 2 * NW) { src = wk; hi = g_wk_hi; lo = g_wk_lo; j = i - NW; }
    else if (i < 3 * NW) { src = wv; hi = g_wv_hi; lo = g_wv_lo; j = i - 2 * NW; }
    else                 { src = wo; hi = g_wo_hi; lo = g_wo_lo; j = i - 3 * NW; }
    float val = src[j];
    f16 h = __float2half_rn(val);
    hi[j] = h;
    lo[j] = __float2half_rn(val - __half2float(h));
}

// ----------------------------------------------------------------------------
// Row softmax fp32 -> fp16   (n == 2048, 256 threads)
// ----------------------------------------------------------------------------
__global__ void softmax_f16(const float* __restrict__ S, f16* __restrict__ P, int n) {
    const float* row = S + (long)blockIdx.x * n;
    __shared__ float red[256];
    const int t = threadIdx.x;
    float e[8];
    float m = -1e30f;
#pragma unroll
    for (int i = 0; i < 8; i++) { e[i] = row[t + i * 256]; m = fmaxf(m, e[i]); }
    red[t] = m; __syncthreads();
    for (int s = 128; s > 0; s >>= 1) {
        if (t < s) red[t] = fmaxf(red[t], red[t + s]);
        __syncthreads();
    }
    m = red[0]; __syncthreads();
    float sum = 0.f;
#pragma unroll
    for (int i = 0; i < 8; i++) { e[i] = __expf(e[i] - m); sum += e[i]; }
    red[t] = sum; __syncthreads();
    for (int s = 128; s > 0; s >>= 1) {
        if (t < s) red[t] += red[t + s];
        __syncthreads();
    }
    float inv = 1.0f / red[0];
#pragma unroll
    for (int i = 0; i < 8; i++)
        P[(long)blockIdx.x * n + t + i * 256] = __float2half_rn(e[i] * inv);
}

// ----------------------------------------------------------------------------
// mma.sync fp16 2-product GEMM (NT):  C[m,n] = alpha * sum_k A[m,k]*B[n,k] (+bias)
//   A single fp16, B = Bh + Bl fp16 pair.
//   CTA tile 128x128, BK=32, 3-stage cp.async (1 sync/chunk), 8 warps (64x32).
//   Chunk-wide LDSM hoist: all fragments loaded before the MMA block.
//   mode 0: fp32 out.  mode 1: fp16 single out.  mode 2: fp16 pair out.
// ----------------------------------------------------------------------------
#define BM 128
#define BN 128
#define BK 32
#define ROWB 80              // smem row stride bytes (32 fp16 = 64B data + 16B pad)
#define TILEB (128 * ROWB)   // 10240 B per matrix tile
#define SM_A  0
#define SM_BH TILEB
#define SM_BL (2 * TILEB)
#define STAGEB (3 * TILEB)   // 30720 B
#define NSTAGE 3
#define SMEM_BYTES (NSTAGE * STAGEB)   // 92160 B

__global__ void __launch_bounds__(256) gemm2(
    const f16* __restrict__ A,
    const f16* __restrict__ Bhi, const f16* __restrict__ Blo,
    const float* __restrict__ bias,
    float* __restrict__ Cf, f16* __restrict__ C1, f16* __restrict__ C2,
    int N, int K, int ldc, float alpha,
    long sA, long sB, long sC, int mode, int transC)
{
    extern __shared__ char smem[];
    const uint32_t sb = smem_u32(smem);
    const int tid = threadIdx.x;
    const int wid = tid >> 5;
    const int lid = tid & 31;
    const int wm = (wid & 1) * 64;       // warp M offset in CTA tile
    const int wn = (wid >> 1) * 32;      // warp N offset
    const long bz = blockIdx.z;
    const int m0 = blockIdx.y * BM;
    const int n0 = blockIdx.x * BN;

    const f16* pA  = A   + bz * sA;
    const f16* pBh = Bhi + bz * sB;
    const f16* pBl = Blo + bz * sB;

    const int lrow = tid >> 2;           // 0..63 base row for loads
    const int lch  = tid & 3;            // 16B chunk 0..3

    float acc[4][4][4];
#pragma unroll
    for (int i = 0; i < 4; ++i)
#pragma unroll
        for (int j = 0; j < 4; ++j)
#pragma unroll
            for (int c = 0; c < 4; ++c) acc[i][j][c] = 0.f;

    const int nch = K / BK;

    // ---- stage loader: 6 x cp.async per thread (2 rows x 3 tiles) ----
    auto issue = [&](int ch, int buf) {
        const int k0 = ch * BK;
        const uint32_t s0 = sb + buf * STAGEB;
#pragma unroll
        for (int h = 0; h < 2; ++h) {
            const int r = lrow + h * 64;
            const uint32_t so = (uint32_t)(r * ROWB + lch * 16);
            const long goA = (long)(m0 + r) * K + k0 + lch * 8;
            const long goB = (long)(n0 + r) * K + k0 + lch * 8;
            cp16(s0 + SM_A  + so, pA  + goA);
            cp16(s0 + SM_BH + so, pBh + goB);
            cp16(s0 + SM_BL + so, pBl + goB);
        }
    };

    issue(0, 0); CP_COMMIT();
    if (nch > 1) { issue(1, 1); CP_COMMIT(); }

    // ldmatrix lane addressing (within a stage buffer)
    const int a_row = lid & 15;                    // 0..15
    const int a_col = (lid >> 4) * 16;             // 0 or 16 bytes
    const int b_nin = ((lid >> 4) & 1) * 8 + (lid & 7);  // n within 16-block
    const int b_col = ((lid >> 3) & 1) * 16;       // k-half bytes

    for (int ch = 0; ch < nch; ++ch) {
        // make stage ch resident
        if (ch + 1 < nch) { CP_WAIT(1); } else { CP_WAIT(0); }
        __syncthreads();
        // refill the stage vacated at iteration ch-1 ((ch+2)%3 == (ch-1)%3);
        // the barrier above guarantees all warps finished reading it.
        if (ch + 2 < nch) { issue(ch + 2, (ch + 2) % NSTAGE); CP_COMMIT(); }

        const uint32_t s0 = sb + (ch % NSTAGE) * STAGEB;

        // ---- chunk-wide fragment loads (both k-steps) ----
        uint32_t af[2][4][4], bh[2][2][4], bl[2][2][4];
#pragma unroll
        for (int ks = 0; ks < 2; ++ks) {
            const int kb = ks * 32 + a_col;
#pragma unroll
            for (int mt = 0; mt < 4; ++mt) {
                const uint32_t ro = (uint32_t)((wm + mt * 16 + a_row) * ROWB);
                ldsm4(af[ks][mt][0], af[ks][mt][1], af[ks][mt][2], af[ks][mt][3],
                      s0 + SM_A + ro + kb);
            }
#pragma unroll
            for (int np = 0; np < 2; ++np) {
                const uint32_t ro = (uint32_t)((wn + np * 16 + b_nin) * ROWB + ks * 32 + b_col);
                ldsm4(bh[ks][np][0], bh[ks][np][1], bh[ks][np][2], bh[ks][np][3],
                      s0 + SM_BH + ro);
                ldsm4(bl[ks][np][0], bl[ks][np][1], bl[ks][np][2], bl[ks][np][3],
                      s0 + SM_BL + ro);
            }
        }
        // ---- MMAs (same accumulation order as R5: ks, mt, nt, hh then hl) ----
#pragma unroll
        for (int ks = 0; ks < 2; ++ks) {
#pragma unroll
            for (int mt = 0; mt < 4; ++mt) {
#pragma unroll
                for (int nt = 0; nt < 4; ++nt) {
                    const int np = nt >> 1, sel = (nt & 1) * 2;
                    mma16816(acc[mt][nt], af[ks][mt], &bh[ks][np][sel]);
                    mma16816(acc[mt][nt], af[ks][mt], &bl[ks][np][sel]);
                }
            }
        }
        // no trailing sync: next iteration's barrier provides the ordering
    }

    // ---- epilogue ----
    const int gr = lid >> 2;             // group row 0..7
    const int tg = lid & 3;              // col pair 0..3
#pragma unroll
    for (int mt = 0; mt < 4; ++mt) {
#pragma unroll
        for (int nt = 0; nt < 4; ++nt) {
#pragma unroll
            for (int h = 0; h < 2; ++h) {        // c0c1 vs c2c3 (row +8)
                const int m = m0 + wm + mt * 16 + gr + h * 8;
#pragma unroll
                for (int c = 0; c < 2; ++c) {
                    const int n = n0 + wn + nt * 8 + tg * 2 + c;
                    float v = acc[mt][nt][h * 2 + c] * alpha;
                    if (bias) v += __ldg(bias + n);
                    if (mode == 0) {
                        Cf[bz * sC + (long)m * ldc + n] = v;
                    } else {
                        long o = transC ? (bz * sC + (long)n * ldc + m)
                                        : (bz * sC + (long)m * ldc + n);
                        f16 hh = __float2half_rn(v);
                        C1[o] = hh;
                        if (mode == 2)
                            C2[o] = __float2half_rn(v - __half2float(hh));
                    }
                }
            }
        }
    }
}

// ----------------------------------------------------------------------------
// launch
// ----------------------------------------------------------------------------
extern "C" void kernel_launch(void* const* d_in, const int* in_sizes, int n_in,
                              void* d_out, int out_size) {
    const float* q  = (const float*)d_in[0];
    const float* k  = (const float*)d_in[1];
    const float* v  = (const float*)d_in[2];
    const float* Wq = (const float*)d_in[3];
    const float* bq = (const float*)d_in[4];
    const float* Wk = (const float*)d_in[5];
    const float* bk = (const float*)d_in[6];
    const float* Wv = (const float*)d_in[7];
    const float* bv = (const float*)d_in[8];
    const float* Wo = (const float*)d_in[9];
    const float* bo = (const float*)d_in[10];
    float* out = (float*)d_out;

    f16 *xq, *xk, *xv, *qp, *at, *av;
    f16 *wqh, *wql, *wkh, *wkl, *wvh, *wvl, *woh, *wol;
    f16 *kph, *kpl, *vTh, *vTl;
    float* sc;
    cudaGetSymbolAddress((void**)&xq, g_xq);
    cudaGetSymbolAddress((void**)&xk, g_xk);
    cudaGetSymbolAddress((void**)&xv, g_xv);
    cudaGetSymbolAddress((void**)&wqh, g_wq_hi); cudaGetSymbolAddress((void**)&wql, g_wq_lo);
    cudaGetSymbolAddress((void**)&wkh, g_wk_hi); cudaGetSymbolAddress((void**)&wkl, g_wk_lo);
    cudaGetSymbolAddress((void**)&wvh, g_wv_hi); cudaGetSymbolAddress((void**)&wvl, g_wv_lo);
    cudaGetSymbolAddress((void**)&woh, g_wo_hi); cudaGetSymbolAddress((void**)&wol, g_wo_lo);
    cudaGetSymbolAddress((void**)&qp, g_qp);
    cudaGetSymbolAddress((void**)&kph, g_kp_hi); cudaGetSymbolAddress((void**)&kpl, g_kp_lo);
    cudaGetSymbolAddress((void**)&vTh, g_vT_hi); cudaGetSymbolAddress((void**)&vTl, g_vT_lo);
    cudaGetSymbolAddress((void**)&at, g_at);
    cudaGetSymbolAddress((void**)&av, g_av);
    cudaGetSymbolAddress((void**)&sc, g_sc);

    cudaFuncSetAttribute(gemm2, cudaFuncAttributeMaxDynamicSharedMemorySize, SMEM_BYTES);

    const int D = DMOD, S = SEQ, B = BATCH;
    dim3 blk(256);
    dim3 gp(D / BN, (B * S) / BM, 1);
    dim3 gv(D / BN, S / BM, B);
    dim3 gs(S / BN, S / BM, B);
    dim3 ga(D / BN, S / BM, B);

    // 1-2: fused conversions
    conv_x3 <<<(unsigned)((3 * NQ + 511) / 512), 512>>>(q, k, v);
    split_w4<<<(unsigned)((4 * NW + 511) / 512), 512>>>(Wq, Wk, Wv, Wo);

    // 3: q projection -> qp (fp16 single)
    gemm2<<<gp, blk, SMEM_BYTES>>>(xq, wqh, wql, bq, nullptr, qp, nullptr,
                                   D, D, D, 1.0f, 0, 0, 0, 1, 0);
    // 4: k projection -> kp (fp16 pair)
    gemm2<<<gp, blk, SMEM_BYTES>>>(xk, wkh, wkl, bk, nullptr, kph, kpl,
                                   D, D, D, 1.0f, 0, 0, 0, 2, 0);
    // 5: v projection -> vT (fp16 pair, transposed [B][D][S])
    gemm2<<<gv, blk, SMEM_BYTES>>>(xv, wvh, wvl, bv, nullptr, vTh, vTl,
                                   D, D, /*ldc=*/S, 1.0f,
                                   (long)S * D, 0, (long)D * S, 2, 1);
    // 6: scores = qp @ kp^T * 0.125 -> fp32
    gemm2<<<gs, blk, SMEM_BYTES>>>(qp, kph, kpl, nullptr, sc, nullptr, nullptr,
                                   S, D, S, 0.125f,
                                   (long)S * D, (long)S * D, (long)S * S, 0, 0);
    // 7: softmax -> fp16 probs
    softmax_f16<<<(unsigned)(B * S), 256>>>(sc, at, S);
    // 8: att = probs @ vT^T -> fp16 single
    gemm2<<<ga, blk, SMEM_BYTES>>>(at, vTh, vTl, nullptr, nullptr, av, nullptr,
                                   D, S, D, 1.0f,
                                   (long)S * S, (long)D * S, (long)S * D, 1, 0);
    // 9: out = att @ Wo^T + bo -> fp32
    gemm2<<<gp, blk, SMEM_BYTES>>>(av, woh, wol, bo, out, nullptr, nullptr,
                                   D, D, D, 1.0f, 0, 0, 0, 0, 0);
}